// round 11
// baseline (speedup 1.0000x reference)
#include <cuda_runtime.h>
#include <cuda_fp16.h>
#include <cstdint>

#define N_SAMP 4096
#define Fh 15
#define Wd 120
#define NWIN 12
#define Sw 10
#define Pn 105
#define HPR 270
#define K1 43200
#define N1 512
#define BK 64
#define NT (K1 / BK)        // 675
#define KSPLIT 15
#define PSTG (NT / KSPLIT)  // 45 stages per piece
#define STAGES 3

// ---------------- device-global scratch (no allocations anywhere) ----------
// k-layout (both A and W): kidx = (h*10+wc)*16 + o   (position-major)
// A = 64*a1 + a2 (fp16 planes); W = w1 + w2/64 (w2 stored pre-scaled by 64)
__device__ __half g_A1[(size_t)N_SAMP * K1];  // 354 MB
__device__ __half g_A2[(size_t)N_SAMP * K1];  // 354 MB
__device__ __half g_W1[(size_t)N1 * K1];      // 44 MB
__device__ __half g_W2[(size_t)N1 * K1];      // 44 MB
__device__ float g_y1s[(size_t)KSPLIT * N_SAMP * N1];  // 126 MB partial sums

// ---------------- helpers ---------------------------------------------------
__device__ __forceinline__ float ffill(float x) {
    unsigned u = __float_as_uint(x);
    return ((u & 0x7f800000u) == 0x7f800000u) ? 0.0f : x;
}
__device__ __forceinline__ uint32_t smem_u32(const void* p) {
    uint32_t a;
    asm("{ .reg .u64 t; cvta.to.shared.u64 t, %1; cvt.u32.u64 %0, t; }" : "=r"(a) : "l"(p));
    return a;
}
#define SWZ(o) ((o) ^ (((o) >> 3) & 0x70))

__device__ __forceinline__ void ldsm4(uint32_t* r, uint32_t addr) {
    asm volatile("ldmatrix.sync.aligned.m8n8.x4.shared.b16 {%0,%1,%2,%3}, [%4];"
                 : "=r"(r[0]), "=r"(r[1]), "=r"(r[2]), "=r"(r[3]) : "r"(addr));
}
__device__ __forceinline__ void hmma_f32(float* d, const uint32_t* a, const uint32_t* b) {
    asm volatile(
        "mma.sync.aligned.m16n8k16.row.col.f32.f16.f16.f32 "
        "{%0,%1,%2,%3},{%4,%5,%6,%7},{%8,%9},{%0,%1,%2,%3};"
        : "+f"(d[0]), "+f"(d[1]), "+f"(d[2]), "+f"(d[3])
        : "r"(a[0]), "r"(a[1]), "r"(a[2]), "r"(a[3]), "r"(b[0]), "r"(b[1]));
}
__device__ __forceinline__ void hmma_f16(uint32_t* d, const uint32_t* a, const uint32_t* b) {
    asm volatile(
        "mma.sync.aligned.m16n8k16.row.col.f16.f16.f16.f16 "
        "{%0,%1},{%2,%3,%4,%5},{%6,%7},{%0,%1};"
        : "+r"(d[0]), "+r"(d[1])
        : "r"(a[0]), "r"(a[1]), "r"(a[2]), "r"(a[3]), "r"(b[0]), "r"(b[1]));
}

// ============================================================================
// Kernel 1 (fused): blocks [0,4096) = features+BN+conv+ReLU -> A planes
//                   blocks [4096, 4096+512) = fc1 weight split+transpose, 1/row
// Shared memory is a union carved from one static buffer.
// ============================================================================
__global__ __launch_bounds__(256) void feat_kernel(
    const float* __restrict__ data,
    const float* __restrict__ bn_gamma, const float* __restrict__ bn_beta,
    const float* __restrict__ bn_mean, const float* __restrict__ bn_var,
    const float* __restrict__ conv_w, const float* __restrict__ conv_b,
    const float* __restrict__ fc1_w)
{
    __shared__ __align__(16) char sbuf[21504];
    const int tid = threadIdx.x;

    if (blockIdx.x >= N_SAMP) {
        // ---- weight-split role: one block per output row n, smem transpose ----
        uint32_t (*sp)[132] = (uint32_t(*)[132])sbuf;  // 16x132 packed (h1,h2)
        const int n = blockIdx.x - N_SAMP;
        const float* wr = fc1_w + (size_t)n * K1;
        unsigned short* w1o = (unsigned short*)g_W1 + (size_t)n * K1;
        unsigned short* w2o = (unsigned short*)g_W2 + (size_t)n * K1;
        const int oh = tid >> 7;     // 0/1: plane selector on writeout
        const int rr = tid & 127;
        for (int rc = 0; rc < 2700; rc += 128) {
            const int r = rc + rr;
            if (r < 2700) {
                #pragma unroll
                for (int oo = 0; oo < 8; oo++) {
                    const int o = oh * 8 + oo;
                    const float w = wr[o * 2700 + r];
                    const __half h1 = __float2half_rn(w);
                    const __half h2 = __float2half_rn((w - __half2float(h1)) * 64.0f);
                    sp[o][rr] = (uint32_t)__half_as_ushort(h1)
                              | ((uint32_t)__half_as_ushort(h2) << 16);
                }
            }
            __syncthreads();
            if (r < 2700) {
                uint32_t u[8];
                #pragma unroll
                for (int o2 = 0; o2 < 8; o2++) {
                    const uint32_t pa = sp[2 * o2][rr];
                    const uint32_t pb = sp[2 * o2 + 1][rr];
                    u[o2] = oh ? ((pa >> 16) | (pb & 0xFFFF0000u))
                               : ((pa & 0xFFFFu) | (pb << 16));
                }
                unsigned short* dst = (oh ? w2o : w1o) + (size_t)r * 16;
                *(uint4*)dst = make_uint4(u[0], u[1], u[2], u[3]);
                *(uint4*)(dst + 8) = make_uint4(u[4], u[5], u[6], u[7]);
            }
            __syncthreads();
        }
        return;
    }

    // ---- feature role (carve the same buffer) ----
    float* sd    = (float*)sbuf;             // 1800 f
    float* sstd  = (float*)(sbuf + 7200);    // 180 f
    float* sfeat = (float*)(sbuf + 7936);    // 3240 f
    float* scw   = (float*)(sbuf + 20896);   // 48 f
    float* scb   = (float*)(sbuf + 21088);   // 16 f

    const int n = blockIdx.x;
    const float* dptr = data + (size_t)n * (Fh * Wd);
    for (int i = tid; i < Fh * Wd; i += 256) sd[i] = dptr[i];
    if (tid < 48) scw[tid] = conv_w[tid];
    if (tid >= 64 && tid < 80) scb[tid - 64] = conv_b[tid - 64];
    const float bscale = rsqrtf(bn_var[0] + 1e-5f) * bn_gamma[0];
    const float bshift = bn_beta[0] - bn_mean[0] * bscale;
    __syncthreads();

    if (tid < Fh * NWIN) {
        const int f = tid / NWIN, w = tid % NWIN;
        float* seg = &sd[f * Wd + w * Sw];
        float mean = 0.f;
        #pragma unroll
        for (int s = 0; s < Sw; s++) mean += seg[s];
        mean *= 0.1f;
        float ret = ffill(seg[Sw - 1] / seg[0] - 1.0f);
        float dl = 0.f;
        #pragma unroll
        for (int s = 0; s < Sw; s++) dl += seg[s] * (float)(s + 1);
        dl *= (1.0f / 55.0f);
        float ss = 0.f;
        #pragma unroll
        for (int s = 0; s < Sw; s++) { float sp2 = seg[s] - mean; seg[s] = sp2; ss += sp2 * sp2; }
        const float sdv = sqrtf(ss * (1.0f / 9.0f));
        sstd[tid] = sdv;
        sfeat[(210 + f) * NWIN + w] = ffill(sdv) * bscale + bshift;
        sfeat[(225 + f) * NWIN + w] = ffill(mean / sdv) * bscale + bshift;
        sfeat[(240 + f) * NWIN + w] = ret * bscale + bshift;
        sfeat[(255 + f) * NWIN + w] = ffill(dl) * bscale + bshift;
    }
    __syncthreads();

    for (int idx = tid; idx < Pn * NWIN; idx += 256) {
        const int p = idx / NWIN, w = idx % NWIN;
        int i = 0, rem = p;
        while (rem >= 14 - i) { rem -= 14 - i; i++; }
        const int j = i + 1 + rem;
        const float* si = &sd[i * Wd + w * Sw];
        const float* sj = &sd[j * Wd + w * Sw];
        float dot = 0.f;
        #pragma unroll
        for (int s = 0; s < Sw; s++) dot += si[s] * sj[s];
        const float cov = dot * (1.0f / 9.0f);
        const float corr = ffill(cov / (sstd[i * NWIN + w] * sstd[j * NWIN + w]) * 0.9f);
        sfeat[p * NWIN + w]         = corr * bscale + bshift;
        sfeat[(105 + p) * NWIN + w] = ffill(cov) * bscale + bshift;
    }
    __syncthreads();

    // Conv + ReLU + fp16 split; position-major layout: kidx = pos*16 + o.
    // One thread per position computes all 16 channels -> 4 dense 16B stores.
    __half* p1 = g_A1 + (size_t)n * K1;
    __half* p2 = g_A2 + (size_t)n * K1;
    for (int pos = tid; pos < 2700; pos += 256) {
        const int h = pos / 10;
        const int wc = pos - h * 10;
        const float* fr = &sfeat[h * NWIN + wc];
        const float f0 = fr[0], f1 = fr[1], f2 = fr[2];
        uint32_t u1[8], u2[8];
        #pragma unroll
        for (int o2 = 0; o2 < 8; o2++) {
            const float va = fmaxf(scb[2*o2]   + scw[6*o2]  *f0 + scw[6*o2+1]*f1 + scw[6*o2+2]*f2, 0.f);
            const float vb = fmaxf(scb[2*o2+1] + scw[6*o2+3]*f0 + scw[6*o2+4]*f1 + scw[6*o2+5]*f2, 0.f);
            const __half a1a = __float2half_rn(va * 0.015625f);
            const __half a1b = __float2half_rn(vb * 0.015625f);
            const __half a2a = __float2half_rn(va - 64.0f * __half2float(a1a));
            const __half a2b = __float2half_rn(vb - 64.0f * __half2float(a1b));
            u1[o2] = (uint32_t)__half_as_ushort(a1a) | ((uint32_t)__half_as_ushort(a1b) << 16);
            u2[o2] = (uint32_t)__half_as_ushort(a2a) | ((uint32_t)__half_as_ushort(a2b) << 16);
        }
        __half* d1 = p1 + (size_t)pos * 16;
        __half* d2 = p2 + (size_t)pos * 16;
        __stcs((uint4*)d1,       make_uint4(u1[0], u1[1], u1[2], u1[3]));
        __stcs((uint4*)(d1 + 8), make_uint4(u1[4], u1[5], u1[6], u1[7]));
        __stcs((uint4*)d2,       make_uint4(u2[0], u2[1], u2[2], u2[3]));
        __stcs((uint4*)(d2 + 8), make_uint4(u2[4], u2[5], u2[6], u2[7]));
    }
}

// ============================================================================
// Kernel 2: fc1 split-fp16 GEMM, split-K over 15 uniform pieces.
// Grid (4 N, 32 M, 15 K) = 1920 identical CTAs (13 rounds on 148 SMs, 0.2% quant).
// Piece output: 64*f32acc + f16cross (raw, no bias/relu) -> g_y1s[kp].
// ============================================================================
__global__ __launch_bounds__(512) void fc1_mma()
{
    extern __shared__ __align__(1024) char smem[];
    const int tid = threadIdx.x;
    const int bx = blockIdx.x;   // N tile 0..3
    const int by = blockIdx.y;   // M tile 0..31
    const int kp = blockIdx.z;   // K piece 0..14
    const int warp = tid >> 5, lane = tid & 31;
    const int wm = warp >> 2;    // 0..3
    const int wn = warp & 3;     // 0..3
    const uint32_t sbase = smem_u32(smem);

    const __half* gp0 = g_A1 + (size_t)(by * 128) * K1;
    const __half* gp1 = g_A2 + (size_t)(by * 128) * K1;
    const __half* gp2 = g_W1 + (size_t)(bx * 128) * K1;
    const __half* gp3 = g_W2 + (size_t)(bx * 128) * K1;
    const int kbeg = kp * PSTG;

    auto issue_stage = [&](int kt, int slot) {
        const int k0 = kt * BK;
        const uint32_t sb = sbase + (uint32_t)slot * 65536u;
        #pragma unroll
        for (int p = 0; p < 8; p++) {
            const int plane = p >> 1;
            const int v = tid + ((p & 1) << 9);
            const int row = v >> 3;
            const int c = v & 7;
            const __half* g =
                (plane == 0 ? gp0 : plane == 1 ? gp1 : plane == 2 ? gp2 : gp3)
                + (size_t)row * K1 + k0 + c * 8;
            const uint32_t sa = sb + (uint32_t)plane * 16384u
                              + SWZ((uint32_t)(row * 128 + c * 16));
            asm volatile("cp.async.cg.shared.global [%0], [%1], 16;"
                         :: "r"(sa), "l"(g));
        }
        asm volatile("cp.async.commit_group;");
    };

    issue_stage(kbeg + 0, 0);
    issue_stage(kbeg + 1, 1);

    float acc[2][4][4];
    uint32_t hacc[2][4][2];
    #pragma unroll
    for (int i = 0; i < 2; i++)
        #pragma unroll
        for (int j = 0; j < 4; j++) {
            #pragma unroll
            for (int q = 0; q < 4; q++) acc[i][j][q] = 0.f;
            hacc[i][j][0] = 0u; hacc[i][j][1] = 0u;
        }

    const uint32_t a_row_off = (uint32_t)((wm * 32 + (lane & 15)) * 128);
    const uint32_t a_k_off   = (uint32_t)((lane >> 4) << 4);
    const uint32_t b_row_off = (uint32_t)((wn * 32 + ((lane >> 4) << 3) + (lane & 7)) * 128);
    const uint32_t b_k_off   = (uint32_t)(((lane >> 3) & 1) << 4);

    for (int it = 0; it < PSTG; it++) {
        asm volatile("cp.async.wait_group 1;");
        __syncthreads();
        if (it + 2 < PSTG) issue_stage(kbeg + it + 2, (it + 2) % STAGES);
        else asm volatile("cp.async.commit_group;");

        const uint32_t sb = sbase + (uint32_t)(it % STAGES) * 65536u;
        #pragma unroll
        for (int s = 0; s < 4; s++) {
            uint32_t a1f[2][4], a2f[2][4];
            #pragma unroll
            for (int mt = 0; mt < 2; mt++) {
                const uint32_t off = a_row_off + mt * 2048 + s * 32 + a_k_off;
                ldsm4(a1f[mt], sb + SWZ(off));
                ldsm4(a2f[mt], sb + 16384u + SWZ(off));
            }
            uint32_t w1f[2][4], w2f[2][4];
            #pragma unroll
            for (int q = 0; q < 2; q++) {
                const uint32_t off = b_row_off + q * 2048 + s * 32 + b_k_off;
                ldsm4(w1f[q], sb + 32768u + SWZ(off));
                ldsm4(w2f[q], sb + 49152u + SWZ(off));
            }
            #pragma unroll
            for (int mt = 0; mt < 2; mt++)
                #pragma unroll
                for (int nt = 0; nt < 4; nt++)
                    hmma_f32(acc[mt][nt], a1f[mt], &w1f[nt >> 1][(nt & 1) << 1]);
            #pragma unroll
            for (int mt = 0; mt < 2; mt++)
                #pragma unroll
                for (int nt = 0; nt < 4; nt++)
                    hmma_f16(hacc[mt][nt], a1f[mt], &w2f[nt >> 1][(nt & 1) << 1]);
            #pragma unroll
            for (int mt = 0; mt < 2; mt++)
                #pragma unroll
                for (int nt = 0; nt < 4; nt++)
                    hmma_f16(hacc[mt][nt], a2f[mt], &w1f[nt >> 1][(nt & 1) << 1]);
        }
    }

    // epilogue: raw partial = 64*main + cross -> piece slice
    float* ybase = g_y1s + (size_t)kp * N_SAMP * N1;
    #pragma unroll
    for (int mt = 0; mt < 2; mt++) {
        const int r0 = by * 128 + wm * 32 + mt * 16 + (lane >> 2);
        #pragma unroll
        for (int nt = 0; nt < 4; nt++) {
            const int c = bx * 128 + wn * 32 + nt * 8 + ((lane & 3) << 1);
            float2 c0 = __half22float2(*(half2*)&hacc[mt][nt][0]);
            float2 c1 = __half22float2(*(half2*)&hacc[mt][nt][1]);
            float2 v0, v1;
            v0.x = 64.0f * acc[mt][nt][0] + c0.x;
            v0.y = 64.0f * acc[mt][nt][1] + c0.y;
            v1.x = 64.0f * acc[mt][nt][2] + c1.x;
            v1.y = 64.0f * acc[mt][nt][3] + c1.y;
            *(float2*)(ybase + (size_t)r0 * N1 + c) = v0;
            *(float2*)(ybase + (size_t)(r0 + 8) * N1 + c) = v1;
        }
    }
}

// ============================================================================
// Kernel 3: fused fc2(sigmoid) + fc3 -- 256 blocks of 16 rows.
// A-load sums the 15 split-K slices, adds fc1 bias, applies ReLU.
// ============================================================================
__global__ __launch_bounds__(256) void fc23_kernel(
    const float* __restrict__ b1,
    const float* __restrict__ w2, const float* __restrict__ b2,
    const float* __restrict__ w3, const float* __restrict__ b3,
    float* __restrict__ out)
{
    __shared__ float As[32][16];
    __shared__ float Bs[32][128];
    __shared__ float sbuf[16][128];
    __shared__ float sw3[128];

    const int tid = threadIdx.x;
    const int mb = blockIdx.x;
    if (tid < 128) sw3[tid] = w3[tid];
    const int tm = tid >> 5;
    const int tn = tid & 31;

    float acc[2][4] = {};
    for (int kt = 0; kt < 16; kt++) {
        const int k0 = kt * 32;
        if (tid < 128) {
            const int row = tid >> 3, kq = (tid & 7) << 2;
            const size_t off = (size_t)(mb * 16 + row) * N1 + k0 + kq;
            float4 a = *(const float4*)(g_y1s + off);
            #pragma unroll
            for (int s = 1; s < KSPLIT; s++) {
                float4 t = *(const float4*)(g_y1s + (size_t)s * N_SAMP * N1 + off);
                a.x += t.x; a.y += t.y; a.z += t.z; a.w += t.w;
            }
            a.x = fmaxf(a.x + b1[k0 + kq + 0], 0.f);
            a.y = fmaxf(a.y + b1[k0 + kq + 1], 0.f);
            a.z = fmaxf(a.z + b1[k0 + kq + 2], 0.f);
            a.w = fmaxf(a.w + b1[k0 + kq + 3], 0.f);
            As[kq + 0][row] = a.x; As[kq + 1][row] = a.y;
            As[kq + 2][row] = a.z; As[kq + 3][row] = a.w;
        }
        #pragma unroll
        for (int q = 0; q < 4; q++) {
            const int v = tid + q * 256;
            const int row = v >> 3, kq = (v & 7) << 2;
            float4 b = *(const float4*)(w2 + (size_t)row * N1 + k0 + kq);
            Bs[kq + 0][row] = b.x; Bs[kq + 1][row] = b.y;
            Bs[kq + 2][row] = b.z; Bs[kq + 3][row] = b.w;
        }
        __syncthreads();
        #pragma unroll
        for (int k = 0; k < 32; k++) {
            float ra[2], rb[4];
            ra[0] = As[k][tm * 2];
            ra[1] = As[k][tm * 2 + 1];
            *(float4*)rb = *(const float4*)&Bs[k][tn * 4];
            #pragma unroll
            for (int i = 0; i < 2; i++)
                #pragma unroll
                for (int j = 0; j < 4; j++) acc[i][j] += ra[i] * rb[j];
        }
        __syncthreads();
    }

    #pragma unroll
    for (int i = 0; i < 2; i++)
        #pragma unroll
        for (int j = 0; j < 4; j++) {
            const float v = acc[i][j] + b2[tn * 4 + j];
            sbuf[tm * 2 + i][tn * 4 + j] = 1.0f / (1.0f + expf(-v));
        }
    __syncthreads();

    #pragma unroll
    for (int r = 0; r < 2; r++) {
        const int row = tm * 2 + r;
        float s = sbuf[row][tn] * sw3[tn] + sbuf[row][tn + 32] * sw3[tn + 32]
                + sbuf[row][tn + 64] * sw3[tn + 64] + sbuf[row][tn + 96] * sw3[tn + 96];
        #pragma unroll
        for (int o = 16; o; o >>= 1) s += __shfl_down_sync(0xffffffffu, s, o);
        if (tn == 0) out[mb * 16 + row] = s + b3[0];
    }
}

// ============================================================================
extern "C" void kernel_launch(void* const* d_in, const int* in_sizes, int n_in,
                              void* d_out, int out_size) {
    const float* data   = (const float*)d_in[0];
    const float* gamma  = (const float*)d_in[1];
    const float* beta   = (const float*)d_in[2];
    const float* mean   = (const float*)d_in[3];
    const float* var    = (const float*)d_in[4];
    const float* conv_w = (const float*)d_in[5];
    const float* conv_b = (const float*)d_in[6];
    const float* fc1_w  = (const float*)d_in[7];
    const float* fc1_b  = (const float*)d_in[8];
    const float* fc2_w  = (const float*)d_in[9];
    const float* fc2_b  = (const float*)d_in[10];
    const float* fc3_w  = (const float*)d_in[11];
    const float* fc3_b  = (const float*)d_in[12];
    float* out = (float*)d_out;

    const int smem_sz = STAGES * 4 * 16384;  // 196608
    cudaFuncSetAttribute(fc1_mma, cudaFuncAttributeMaxDynamicSharedMemorySize, smem_sz);

    feat_kernel<<<N_SAMP + N1, 256>>>(data, gamma, beta, mean, var,
                                      conv_w, conv_b, fc1_w);
    dim3 g1(4, 32, KSPLIT);
    fc1_mma<<<g1, 512, smem_sz>>>();
    fc23_kernel<<<256, 256>>>(fc1_b, fc2_w, fc2_b, fc3_w, fc3_b, out);
}

// round 12
// speedup vs baseline: 1.0039x; 1.0039x over previous
#include <cuda_runtime.h>
#include <cuda_fp16.h>
#include <cstdint>

#define N_SAMP 4096
#define Fh 15
#define Wd 120
#define NWIN 12
#define Sw 10
#define Pn 105
#define HPR 270
#define K1 43200
#define N1 512
#define BK 64
#define NT (K1 / BK)        // 675
#define KSPLIT 15
#define PSTG (NT / KSPLIT)  // 45 stages per piece
#define STAGES 3
#define WBLK 2048           // weight-split blocks: 512 rows x 4 r-chunks

// ---------------- device-global scratch (no allocations anywhere) ----------
// k-layout (both A and W): kidx = (h*10+wc)*16 + o   (position-major)
// A = 64*a1 + a2 (fp16 planes); W = w1 + w2/64 (w2 stored pre-scaled by 64)
__device__ __half g_A1[(size_t)N_SAMP * K1];  // 354 MB
__device__ __half g_A2[(size_t)N_SAMP * K1];  // 354 MB
__device__ __half g_W1[(size_t)N1 * K1];      // 44 MB
__device__ __half g_W2[(size_t)N1 * K1];      // 44 MB
__device__ float g_y1s[(size_t)KSPLIT * N_SAMP * N1];  // 126 MB partial sums

// ---------------- helpers ---------------------------------------------------
__device__ __forceinline__ float ffill(float x) {
    unsigned u = __float_as_uint(x);
    return ((u & 0x7f800000u) == 0x7f800000u) ? 0.0f : x;
}
__device__ __forceinline__ uint32_t smem_u32(const void* p) {
    uint32_t a;
    asm("{ .reg .u64 t; cvta.to.shared.u64 t, %1; cvt.u32.u64 %0, t; }" : "=r"(a) : "l"(p));
    return a;
}
#define SWZ(o) ((o) ^ (((o) >> 3) & 0x70))

__device__ __forceinline__ void ldsm4(uint32_t* r, uint32_t addr) {
    asm volatile("ldmatrix.sync.aligned.m8n8.x4.shared.b16 {%0,%1,%2,%3}, [%4];"
                 : "=r"(r[0]), "=r"(r[1]), "=r"(r[2]), "=r"(r[3]) : "r"(addr));
}
__device__ __forceinline__ void hmma_f32(float* d, const uint32_t* a, const uint32_t* b) {
    asm volatile(
        "mma.sync.aligned.m16n8k16.row.col.f32.f16.f16.f32 "
        "{%0,%1,%2,%3},{%4,%5,%6,%7},{%8,%9},{%0,%1,%2,%3};"
        : "+f"(d[0]), "+f"(d[1]), "+f"(d[2]), "+f"(d[3])
        : "r"(a[0]), "r"(a[1]), "r"(a[2]), "r"(a[3]), "r"(b[0]), "r"(b[1]));
}
__device__ __forceinline__ void hmma_f16(uint32_t* d, const uint32_t* a, const uint32_t* b) {
    asm volatile(
        "mma.sync.aligned.m16n8k16.row.col.f16.f16.f16.f16 "
        "{%0,%1},{%2,%3,%4,%5},{%6,%7},{%0,%1};"
        : "+r"(d[0]), "+r"(d[1])
        : "r"(a[0]), "r"(a[1]), "r"(a[2]), "r"(a[3]), "r"(b[0]), "r"(b[1]));
}

// ============================================================================
// Kernel 1 (fused): blocks [0,4096) = features+BN+conv+ReLU -> A planes
//   blocks [4096, 4096+2048): weight split+transpose; block = (n, quarter),
//   each handles 675 k-rows of one output row -> light, backfills SMs.
// ============================================================================
__global__ __launch_bounds__(256) void feat_kernel(
    const float* __restrict__ data,
    const float* __restrict__ bn_gamma, const float* __restrict__ bn_beta,
    const float* __restrict__ bn_mean, const float* __restrict__ bn_var,
    const float* __restrict__ conv_w, const float* __restrict__ conv_b,
    const float* __restrict__ fc1_w)
{
    __shared__ __align__(16) char sbuf[21504];
    const int tid = threadIdx.x;

    if (blockIdx.x >= N_SAMP) {
        // ---- weight-split role ----
        uint32_t (*sp)[132] = (uint32_t(*)[132])sbuf;  // 16x132 packed (h1,h2)
        const int wb = blockIdx.x - N_SAMP;
        const int n = wb >> 2;
        const int qr = wb & 3;
        const int rbeg = qr * 675;
        const int rend = rbeg + 675;
        const float* wr = fc1_w + (size_t)n * K1;
        unsigned short* w1o = (unsigned short*)g_W1 + (size_t)n * K1;
        unsigned short* w2o = (unsigned short*)g_W2 + (size_t)n * K1;
        const int oh = tid >> 7;     // 0/1: plane selector on writeout
        const int rr = tid & 127;
        for (int rc = rbeg; rc < rend; rc += 128) {
            const int r = rc + rr;
            if (r < rend) {
                #pragma unroll
                for (int oo = 0; oo < 8; oo++) {
                    const int o = oh * 8 + oo;
                    const float w = wr[o * 2700 + r];
                    const __half h1 = __float2half_rn(w);
                    const __half h2 = __float2half_rn((w - __half2float(h1)) * 64.0f);
                    sp[o][rr] = (uint32_t)__half_as_ushort(h1)
                              | ((uint32_t)__half_as_ushort(h2) << 16);
                }
            }
            __syncthreads();
            if (r < rend) {
                uint32_t u[8];
                #pragma unroll
                for (int o2 = 0; o2 < 8; o2++) {
                    const uint32_t pa = sp[2 * o2][rr];
                    const uint32_t pb = sp[2 * o2 + 1][rr];
                    u[o2] = oh ? ((pa >> 16) | (pb & 0xFFFF0000u))
                               : ((pa & 0xFFFFu) | (pb << 16));
                }
                unsigned short* dst = (oh ? w2o : w1o) + (size_t)r * 16;
                *(uint4*)dst = make_uint4(u[0], u[1], u[2], u[3]);
                *(uint4*)(dst + 8) = make_uint4(u[4], u[5], u[6], u[7]);
            }
            __syncthreads();
        }
        return;
    }

    // ---- feature role (carve the same buffer) ----
    float* sd    = (float*)sbuf;             // 1800 f
    float* sstd  = (float*)(sbuf + 7200);    // 180 f
    float* sfeat = (float*)(sbuf + 7936);    // 3240 f
    float* scw   = (float*)(sbuf + 20896);   // 48 f
    float* scb   = (float*)(sbuf + 21088);   // 16 f

    const int n = blockIdx.x;
    const float* dptr = data + (size_t)n * (Fh * Wd);
    for (int i = tid; i < Fh * Wd; i += 256) sd[i] = dptr[i];
    if (tid < 48) scw[tid] = conv_w[tid];
    if (tid >= 64 && tid < 80) scb[tid - 64] = conv_b[tid - 64];
    const float bscale = rsqrtf(bn_var[0] + 1e-5f) * bn_gamma[0];
    const float bshift = bn_beta[0] - bn_mean[0] * bscale;
    __syncthreads();

    if (tid < Fh * NWIN) {
        const int f = tid / NWIN, w = tid % NWIN;
        float* seg = &sd[f * Wd + w * Sw];
        float mean = 0.f;
        #pragma unroll
        for (int s = 0; s < Sw; s++) mean += seg[s];
        mean *= 0.1f;
        float ret = ffill(seg[Sw - 1] / seg[0] - 1.0f);
        float dl = 0.f;
        #pragma unroll
        for (int s = 0; s < Sw; s++) dl += seg[s] * (float)(s + 1);
        dl *= (1.0f / 55.0f);
        float ss = 0.f;
        #pragma unroll
        for (int s = 0; s < Sw; s++) { float sp2 = seg[s] - mean; seg[s] = sp2; ss += sp2 * sp2; }
        const float sdv = sqrtf(ss * (1.0f / 9.0f));
        sstd[tid] = sdv;
        sfeat[(210 + f) * NWIN + w] = ffill(sdv) * bscale + bshift;
        sfeat[(225 + f) * NWIN + w] = ffill(mean / sdv) * bscale + bshift;
        sfeat[(240 + f) * NWIN + w] = ret * bscale + bshift;
        sfeat[(255 + f) * NWIN + w] = ffill(dl) * bscale + bshift;
    }
    __syncthreads();

    for (int idx = tid; idx < Pn * NWIN; idx += 256) {
        const int p = idx / NWIN, w = idx % NWIN;
        int i = 0, rem = p;
        while (rem >= 14 - i) { rem -= 14 - i; i++; }
        const int j = i + 1 + rem;
        const float* si = &sd[i * Wd + w * Sw];
        const float* sj = &sd[j * Wd + w * Sw];
        float dot = 0.f;
        #pragma unroll
        for (int s = 0; s < Sw; s++) dot += si[s] * sj[s];
        const float cov = dot * (1.0f / 9.0f);
        const float corr = ffill(cov / (sstd[i * NWIN + w] * sstd[j * NWIN + w]) * 0.9f);
        sfeat[p * NWIN + w]         = corr * bscale + bshift;
        sfeat[(105 + p) * NWIN + w] = ffill(cov) * bscale + bshift;
    }
    __syncthreads();

    // Conv + ReLU + fp16 split; position-major: kidx = pos*16 + o.
    // One thread per position computes all 16 channels -> 4 dense 16B stores.
    __half* p1 = g_A1 + (size_t)n * K1;
    __half* p2 = g_A2 + (size_t)n * K1;
    for (int pos = tid; pos < 2700; pos += 256) {
        const int h = pos / 10;
        const int wc = pos - h * 10;
        const float* fr = &sfeat[h * NWIN + wc];
        const float f0 = fr[0], f1 = fr[1], f2 = fr[2];
        uint32_t u1[8], u2[8];
        #pragma unroll
        for (int o2 = 0; o2 < 8; o2++) {
            const float va = fmaxf(scb[2*o2]   + scw[6*o2]  *f0 + scw[6*o2+1]*f1 + scw[6*o2+2]*f2, 0.f);
            const float vb = fmaxf(scb[2*o2+1] + scw[6*o2+3]*f0 + scw[6*o2+4]*f1 + scw[6*o2+5]*f2, 0.f);
            const __half a1a = __float2half_rn(va * 0.015625f);
            const __half a1b = __float2half_rn(vb * 0.015625f);
            const __half a2a = __float2half_rn(va - 64.0f * __half2float(a1a));
            const __half a2b = __float2half_rn(vb - 64.0f * __half2float(a1b));
            u1[o2] = (uint32_t)__half_as_ushort(a1a) | ((uint32_t)__half_as_ushort(a1b) << 16);
            u2[o2] = (uint32_t)__half_as_ushort(a2a) | ((uint32_t)__half_as_ushort(a2b) << 16);
        }
        __half* d1 = p1 + (size_t)pos * 16;
        __half* d2 = p2 + (size_t)pos * 16;
        __stcs((uint4*)d1,       make_uint4(u1[0], u1[1], u1[2], u1[3]));
        __stcs((uint4*)(d1 + 8), make_uint4(u1[4], u1[5], u1[6], u1[7]));
        __stcs((uint4*)d2,       make_uint4(u2[0], u2[1], u2[2], u2[3]));
        __stcs((uint4*)(d2 + 8), make_uint4(u2[4], u2[5], u2[6], u2[7]));
    }
}

// ============================================================================
// Kernel 2: fc1 split-fp16 GEMM, split-K over 15 uniform pieces.
// Grid (4 N, 32 M, 15 K) = 1920 identical CTAs (13 rounds on 148 SMs).
// Piece output: 64*f32acc + f16cross (raw) -> g_y1s[kp], streaming stores.
// ============================================================================
__global__ __launch_bounds__(512) void fc1_mma()
{
    extern __shared__ __align__(1024) char smem[];
    const int tid = threadIdx.x;
    const int bx = blockIdx.x;   // N tile 0..3
    const int by = blockIdx.y;   // M tile 0..31
    const int kp = blockIdx.z;   // K piece 0..14
    const int warp = tid >> 5, lane = tid & 31;
    const int wm = warp >> 2;    // 0..3
    const int wn = warp & 3;     // 0..3
    const uint32_t sbase = smem_u32(smem);

    const __half* gp0 = g_A1 + (size_t)(by * 128) * K1;
    const __half* gp1 = g_A2 + (size_t)(by * 128) * K1;
    const __half* gp2 = g_W1 + (size_t)(bx * 128) * K1;
    const __half* gp3 = g_W2 + (size_t)(bx * 128) * K1;
    const int kbeg = kp * PSTG;

    auto issue_stage = [&](int kt, int slot) {
        const int k0 = kt * BK;
        const uint32_t sb = sbase + (uint32_t)slot * 65536u;
        #pragma unroll
        for (int p = 0; p < 8; p++) {
            const int plane = p >> 1;
            const int v = tid + ((p & 1) << 9);
            const int row = v >> 3;
            const int c = v & 7;
            const __half* g =
                (plane == 0 ? gp0 : plane == 1 ? gp1 : plane == 2 ? gp2 : gp3)
                + (size_t)row * K1 + k0 + c * 8;
            const uint32_t sa = sb + (uint32_t)plane * 16384u
                              + SWZ((uint32_t)(row * 128 + c * 16));
            asm volatile("cp.async.cg.shared.global [%0], [%1], 16;"
                         :: "r"(sa), "l"(g));
        }
        asm volatile("cp.async.commit_group;");
    };

    issue_stage(kbeg + 0, 0);
    issue_stage(kbeg + 1, 1);

    float acc[2][4][4];
    uint32_t hacc[2][4][2];
    #pragma unroll
    for (int i = 0; i < 2; i++)
        #pragma unroll
        for (int j = 0; j < 4; j++) {
            #pragma unroll
            for (int q = 0; q < 4; q++) acc[i][j][q] = 0.f;
            hacc[i][j][0] = 0u; hacc[i][j][1] = 0u;
        }

    const uint32_t a_row_off = (uint32_t)((wm * 32 + (lane & 15)) * 128);
    const uint32_t a_k_off   = (uint32_t)((lane >> 4) << 4);
    const uint32_t b_row_off = (uint32_t)((wn * 32 + ((lane >> 4) << 3) + (lane & 7)) * 128);
    const uint32_t b_k_off   = (uint32_t)(((lane >> 3) & 1) << 4);

    for (int it = 0; it < PSTG; it++) {
        asm volatile("cp.async.wait_group 1;");
        __syncthreads();
        if (it + 2 < PSTG) issue_stage(kbeg + it + 2, (it + 2) % STAGES);
        else asm volatile("cp.async.commit_group;");

        const uint32_t sb = sbase + (uint32_t)(it % STAGES) * 65536u;
        #pragma unroll
        for (int s = 0; s < 4; s++) {
            uint32_t a1f[2][4], a2f[2][4];
            #pragma unroll
            for (int mt = 0; mt < 2; mt++) {
                const uint32_t off = a_row_off + mt * 2048 + s * 32 + a_k_off;
                ldsm4(a1f[mt], sb + SWZ(off));
                ldsm4(a2f[mt], sb + 16384u + SWZ(off));
            }
            uint32_t w1f[2][4], w2f[2][4];
            #pragma unroll
            for (int q = 0; q < 2; q++) {
                const uint32_t off = b_row_off + q * 2048 + s * 32 + b_k_off;
                ldsm4(w1f[q], sb + 32768u + SWZ(off));
                ldsm4(w2f[q], sb + 49152u + SWZ(off));
            }
            #pragma unroll
            for (int mt = 0; mt < 2; mt++)
                #pragma unroll
                for (int nt = 0; nt < 4; nt++)
                    hmma_f32(acc[mt][nt], a1f[mt], &w1f[nt >> 1][(nt & 1) << 1]);
            #pragma unroll
            for (int mt = 0; mt < 2; mt++)
                #pragma unroll
                for (int nt = 0; nt < 4; nt++)
                    hmma_f16(hacc[mt][nt], a1f[mt], &w2f[nt >> 1][(nt & 1) << 1]);
            #pragma unroll
            for (int mt = 0; mt < 2; mt++)
                #pragma unroll
                for (int nt = 0; nt < 4; nt++)
                    hmma_f16(hacc[mt][nt], a2f[mt], &w1f[nt >> 1][(nt & 1) << 1]);
        }
    }

    // epilogue: raw partial = 64*main + cross -> piece slice (streaming)
    float* ybase = g_y1s + (size_t)kp * N_SAMP * N1;
    #pragma unroll
    for (int mt = 0; mt < 2; mt++) {
        const int r0 = by * 128 + wm * 32 + mt * 16 + (lane >> 2);
        #pragma unroll
        for (int nt = 0; nt < 4; nt++) {
            const int c = bx * 128 + wn * 32 + nt * 8 + ((lane & 3) << 1);
            float2 c0 = __half22float2(*(half2*)&hacc[mt][nt][0]);
            float2 c1 = __half22float2(*(half2*)&hacc[mt][nt][1]);
            float2 v0, v1;
            v0.x = 64.0f * acc[mt][nt][0] + c0.x;
            v0.y = 64.0f * acc[mt][nt][1] + c0.y;
            v1.x = 64.0f * acc[mt][nt][2] + c1.x;
            v1.y = 64.0f * acc[mt][nt][3] + c1.y;
            __stcs((float2*)(ybase + (size_t)r0 * N1 + c), v0);
            __stcs((float2*)(ybase + (size_t)(r0 + 8) * N1 + c), v1);
        }
    }
}

// ============================================================================
// Kernel 3: fused fc2(sigmoid) + fc3 -- 256 blocks of 16 rows.
// A-load sums the 15 split-K slices, adds fc1 bias, applies ReLU.
// ============================================================================
__global__ __launch_bounds__(256) void fc23_kernel(
    const float* __restrict__ b1,
    const float* __restrict__ w2, const float* __restrict__ b2,
    const float* __restrict__ w3, const float* __restrict__ b3,
    float* __restrict__ out)
{
    __shared__ float As[32][16];
    __shared__ float Bs[32][128];
    __shared__ float sbuf[16][128];
    __shared__ float sw3[128];

    const int tid = threadIdx.x;
    const int mb = blockIdx.x;
    if (tid < 128) sw3[tid] = w3[tid];
    const int tm = tid >> 5;
    const int tn = tid & 31;

    float acc[2][4] = {};
    for (int kt = 0; kt < 16; kt++) {
        const int k0 = kt * 32;
        if (tid < 128) {
            const int row = tid >> 3, kq = (tid & 7) << 2;
            const size_t off = (size_t)(mb * 16 + row) * N1 + k0 + kq;
            float4 a = *(const float4*)(g_y1s + off);
            #pragma unroll
            for (int s = 1; s < KSPLIT; s++) {
                float4 t = *(const float4*)(g_y1s + (size_t)s * N_SAMP * N1 + off);
                a.x += t.x; a.y += t.y; a.z += t.z; a.w += t.w;
            }
            a.x = fmaxf(a.x + b1[k0 + kq + 0], 0.f);
            a.y = fmaxf(a.y + b1[k0 + kq + 1], 0.f);
            a.z = fmaxf(a.z + b1[k0 + kq + 2], 0.f);
            a.w = fmaxf(a.w + b1[k0 + kq + 3], 0.f);
            As[kq + 0][row] = a.x; As[kq + 1][row] = a.y;
            As[kq + 2][row] = a.z; As[kq + 3][row] = a.w;
        }
        #pragma unroll
        for (int q = 0; q < 4; q++) {
            const int v = tid + q * 256;
            const int row = v >> 3, kq = (v & 7) << 2;
            float4 b = *(const float4*)(w2 + (size_t)row * N1 + k0 + kq);
            Bs[kq + 0][row] = b.x; Bs[kq + 1][row] = b.y;
            Bs[kq + 2][row] = b.z; Bs[kq + 3][row] = b.w;
        }
        __syncthreads();
        #pragma unroll
        for (int k = 0; k < 32; k++) {
            float ra[2], rb[4];
            ra[0] = As[k][tm * 2];
            ra[1] = As[k][tm * 2 + 1];
            *(float4*)rb = *(const float4*)&Bs[k][tn * 4];
            #pragma unroll
            for (int i = 0; i < 2; i++)
                #pragma unroll
                for (int j = 0; j < 4; j++) acc[i][j] += ra[i] * rb[j];
        }
        __syncthreads();
    }

    #pragma unroll
    for (int i = 0; i < 2; i++)
        #pragma unroll
        for (int j = 0; j < 4; j++) {
            const float v = acc[i][j] + b2[tn * 4 + j];
            sbuf[tm * 2 + i][tn * 4 + j] = 1.0f / (1.0f + expf(-v));
        }
    __syncthreads();

    #pragma unroll
    for (int r = 0; r < 2; r++) {
        const int row = tm * 2 + r;
        float s = sbuf[row][tn] * sw3[tn] + sbuf[row][tn + 32] * sw3[tn + 32]
                + sbuf[row][tn + 64] * sw3[tn + 64] + sbuf[row][tn + 96] * sw3[tn + 96];
        #pragma unroll
        for (int o = 16; o; o >>= 1) s += __shfl_down_sync(0xffffffffu, s, o);
        if (tn == 0) out[mb * 16 + row] = s + b3[0];
    }
}

// ============================================================================
extern "C" void kernel_launch(void* const* d_in, const int* in_sizes, int n_in,
                              void* d_out, int out_size) {
    const float* data   = (const float*)d_in[0];
    const float* gamma  = (const float*)d_in[1];
    const float* beta   = (const float*)d_in[2];
    const float* mean   = (const float*)d_in[3];
    const float* var    = (const float*)d_in[4];
    const float* conv_w = (const float*)d_in[5];
    const float* conv_b = (const float*)d_in[6];
    const float* fc1_w  = (const float*)d_in[7];
    const float* fc1_b  = (const float*)d_in[8];
    const float* fc2_w  = (const float*)d_in[9];
    const float* fc2_b  = (const float*)d_in[10];
    const float* fc3_w  = (const float*)d_in[11];
    const float* fc3_b  = (const float*)d_in[12];
    float* out = (float*)d_out;

    const int smem_sz = STAGES * 4 * 16384;  // 196608
    cudaFuncSetAttribute(fc1_mma, cudaFuncAttributeMaxDynamicSharedMemorySize, smem_sz);

    feat_kernel<<<N_SAMP + WBLK, 256>>>(data, gamma, beta, mean, var,
                                        conv_w, conv_b, fc1_w);
    dim3 g1(4, 32, KSPLIT);
    fc1_mma<<<g1, 512, smem_sz>>>();
    fc23_kernel<<<256, 256>>>(fc1_b, fc2_w, fc2_b, fc3_w, fc3_b, out);
}

// round 13
// speedup vs baseline: 1.0096x; 1.0056x over previous
#include <cuda_runtime.h>
#include <cuda_fp16.h>
#include <cstdint>

#define N_SAMP 4096
#define Fh 15
#define Wd 120
#define NWIN 12
#define Sw 10
#define Pn 105
#define HPR 270
#define K1 43200
#define N1 512
#define BK 64
#define NT (K1 / BK)        // 675
#define KSPLIT 15
#define PSTG (NT / KSPLIT)  // 45 stages per piece
#define STAGES 3
#define WBLK 2048           // weight-split blocks: 512 rows x 4 r-chunks

// ---------------- device-global scratch (no allocations anywhere) ----------
// k-layout (both A and W): kidx = (h*10+wc)*16 + o   (position-major)
// A = 64*a1 + a2 (fp16 planes); W = w1 + w2/64 (w2 stored pre-scaled by 64)
__device__ __half g_A1[(size_t)N_SAMP * K1];  // 354 MB
__device__ __half g_A2[(size_t)N_SAMP * K1];  // 354 MB
__device__ __half g_W1[(size_t)N1 * K1];      // 44 MB
__device__ __half g_W2[(size_t)N1 * K1];      // 44 MB
__device__ float g_y1s[(size_t)KSPLIT * N_SAMP * N1];  // 126 MB partial sums
__device__ float g_y1[(size_t)N_SAMP * N1];   // 8 MB final fc1 output
__device__ int   g_cnt[128];                  // per-tile arrival counters (zero-init)

// ---------------- helpers ---------------------------------------------------
__device__ __forceinline__ float ffill(float x) {
    unsigned u = __float_as_uint(x);
    return ((u & 0x7f800000u) == 0x7f800000u) ? 0.0f : x;
}
__device__ __forceinline__ uint32_t smem_u32(const void* p) {
    uint32_t a;
    asm("{ .reg .u64 t; cvta.to.shared.u64 t, %1; cvt.u32.u64 %0, t; }" : "=r"(a) : "l"(p));
    return a;
}
#define SWZ(o) ((o) ^ (((o) >> 3) & 0x70))

__device__ __forceinline__ void ldsm4(uint32_t* r, uint32_t addr) {
    asm volatile("ldmatrix.sync.aligned.m8n8.x4.shared.b16 {%0,%1,%2,%3}, [%4];"
                 : "=r"(r[0]), "=r"(r[1]), "=r"(r[2]), "=r"(r[3]) : "r"(addr));
}
__device__ __forceinline__ void hmma_f32(float* d, const uint32_t* a, const uint32_t* b) {
    asm volatile(
        "mma.sync.aligned.m16n8k16.row.col.f32.f16.f16.f32 "
        "{%0,%1,%2,%3},{%4,%5,%6,%7},{%8,%9},{%0,%1,%2,%3};"
        : "+f"(d[0]), "+f"(d[1]), "+f"(d[2]), "+f"(d[3])
        : "r"(a[0]), "r"(a[1]), "r"(a[2]), "r"(a[3]), "r"(b[0]), "r"(b[1]));
}
__device__ __forceinline__ void hmma_f16(uint32_t* d, const uint32_t* a, const uint32_t* b) {
    asm volatile(
        "mma.sync.aligned.m16n8k16.row.col.f16.f16.f16.f16 "
        "{%0,%1},{%2,%3,%4,%5},{%6,%7},{%0,%1};"
        : "+r"(d[0]), "+r"(d[1])
        : "r"(a[0]), "r"(a[1]), "r"(a[2]), "r"(a[3]), "r"(b[0]), "r"(b[1]));
}

// ============================================================================
// Kernel 1 (fused): blocks [0,4096) = features+BN+conv+ReLU -> A planes
//   blocks [4096, 4096+2048): weight split+transpose; block = (n, quarter).
// ============================================================================
__global__ __launch_bounds__(256) void feat_kernel(
    const float* __restrict__ data,
    const float* __restrict__ bn_gamma, const float* __restrict__ bn_beta,
    const float* __restrict__ bn_mean, const float* __restrict__ bn_var,
    const float* __restrict__ conv_w, const float* __restrict__ conv_b,
    const float* __restrict__ fc1_w)
{
    __shared__ __align__(16) char sbuf[21504];
    const int tid = threadIdx.x;

    if (blockIdx.x >= N_SAMP) {
        // ---- weight-split role ----
        uint32_t (*sp)[132] = (uint32_t(*)[132])sbuf;  // 16x132 packed (h1,h2)
        const int wb = blockIdx.x - N_SAMP;
        const int n = wb >> 2;
        const int qr = wb & 3;
        const int rbeg = qr * 675;
        const int rend = rbeg + 675;
        const float* wr = fc1_w + (size_t)n * K1;
        unsigned short* w1o = (unsigned short*)g_W1 + (size_t)n * K1;
        unsigned short* w2o = (unsigned short*)g_W2 + (size_t)n * K1;
        const int oh = tid >> 7;
        const int rr = tid & 127;
        for (int rc = rbeg; rc < rend; rc += 128) {
            const int r = rc + rr;
            if (r < rend) {
                #pragma unroll
                for (int oo = 0; oo < 8; oo++) {
                    const int o = oh * 8 + oo;
                    const float w = wr[o * 2700 + r];
                    const __half h1 = __float2half_rn(w);
                    const __half h2 = __float2half_rn((w - __half2float(h1)) * 64.0f);
                    sp[o][rr] = (uint32_t)__half_as_ushort(h1)
                              | ((uint32_t)__half_as_ushort(h2) << 16);
                }
            }
            __syncthreads();
            if (r < rend) {
                uint32_t u[8];
                #pragma unroll
                for (int o2 = 0; o2 < 8; o2++) {
                    const uint32_t pa = sp[2 * o2][rr];
                    const uint32_t pb = sp[2 * o2 + 1][rr];
                    u[o2] = oh ? ((pa >> 16) | (pb & 0xFFFF0000u))
                               : ((pa & 0xFFFFu) | (pb << 16));
                }
                unsigned short* dst = (oh ? w2o : w1o) + (size_t)r * 16;
                *(uint4*)dst = make_uint4(u[0], u[1], u[2], u[3]);
                *(uint4*)(dst + 8) = make_uint4(u[4], u[5], u[6], u[7]);
            }
            __syncthreads();
        }
        return;
    }

    // ---- feature role (carve the same buffer) ----
    float* sd    = (float*)sbuf;             // 1800 f
    float* sstd  = (float*)(sbuf + 7200);    // 180 f
    float* sfeat = (float*)(sbuf + 7936);    // 3240 f
    float* scw   = (float*)(sbuf + 20896);   // 48 f
    float* scb   = (float*)(sbuf + 21088);   // 16 f
    unsigned char* sij = (unsigned char*)(sbuf + 21152);  // 210 B pair LUT

    const int n = blockIdx.x;
    const float* dptr = data + (size_t)n * (Fh * Wd);
    for (int i = tid; i < Fh * Wd; i += 256) sd[i] = dptr[i];
    if (tid < 48) scw[tid] = conv_w[tid];
    if (tid >= 64 && tid < 80) scb[tid - 64] = conv_b[tid - 64];
    const float bscale = rsqrtf(bn_var[0] + 1e-5f) * bn_gamma[0];
    const float bshift = bn_beta[0] - bn_mean[0] * bscale;
    // pair-decode LUT (one decode per pair, instead of per (pair,window) item)
    if (tid >= 128 && tid < 128 + Pn) {
        const int p = tid - 128;
        int i = 0, rem = p;
        while (rem >= 14 - i) { rem -= 14 - i; i++; }
        sij[2 * p] = (unsigned char)i;
        sij[2 * p + 1] = (unsigned char)(i + 1 + rem);
    }
    __syncthreads();

    if (tid < Fh * NWIN) {
        const int f = tid / NWIN, w = tid % NWIN;
        float* seg = &sd[f * Wd + w * Sw];
        float mean = 0.f;
        #pragma unroll
        for (int s = 0; s < Sw; s++) mean += seg[s];
        mean *= 0.1f;
        float ret = ffill(seg[Sw - 1] / seg[0] - 1.0f);
        float dl = 0.f;
        #pragma unroll
        for (int s = 0; s < Sw; s++) dl += seg[s] * (float)(s + 1);
        dl *= (1.0f / 55.0f);
        float ss = 0.f;
        #pragma unroll
        for (int s = 0; s < Sw; s++) { float sp2 = seg[s] - mean; seg[s] = sp2; ss += sp2 * sp2; }
        const float sdv = sqrtf(ss * (1.0f / 9.0f));
        sstd[tid] = sdv;
        sfeat[(210 + f) * NWIN + w] = ffill(sdv) * bscale + bshift;
        sfeat[(225 + f) * NWIN + w] = ffill(mean / sdv) * bscale + bshift;
        sfeat[(240 + f) * NWIN + w] = ret * bscale + bshift;
        sfeat[(255 + f) * NWIN + w] = ffill(dl) * bscale + bshift;
    }
    __syncthreads();

    for (int idx = tid; idx < Pn * NWIN; idx += 256) {
        const int p = idx / NWIN, w = idx % NWIN;
        const int i = sij[2 * p];
        const int j = sij[2 * p + 1];
        const float* si = &sd[i * Wd + w * Sw];
        const float* sj = &sd[j * Wd + w * Sw];
        float dot = 0.f;
        #pragma unroll
        for (int s = 0; s < Sw; s++) dot += si[s] * sj[s];
        const float cov = dot * (1.0f / 9.0f);
        const float corr = ffill(cov / (sstd[i * NWIN + w] * sstd[j * NWIN + w]) * 0.9f);
        sfeat[p * NWIN + w]         = corr * bscale + bshift;
        sfeat[(105 + p) * NWIN + w] = ffill(cov) * bscale + bshift;
    }
    __syncthreads();

    // Conv + ReLU + fp16 split; position-major: kidx = pos*16 + o.
    __half* p1 = g_A1 + (size_t)n * K1;
    __half* p2 = g_A2 + (size_t)n * K1;
    for (int pos = tid; pos < 2700; pos += 256) {
        const int h = pos / 10;
        const int wc = pos - h * 10;
        const float* fr = &sfeat[h * NWIN + wc];
        const float f0 = fr[0], f1 = fr[1], f2 = fr[2];
        uint32_t u1[8], u2[8];
        #pragma unroll
        for (int o2 = 0; o2 < 8; o2++) {
            const float va = fmaxf(scb[2*o2]   + scw[6*o2]  *f0 + scw[6*o2+1]*f1 + scw[6*o2+2]*f2, 0.f);
            const float vb = fmaxf(scb[2*o2+1] + scw[6*o2+3]*f0 + scw[6*o2+4]*f1 + scw[6*o2+5]*f2, 0.f);
            const __half a1a = __float2half_rn(va * 0.015625f);
            const __half a1b = __float2half_rn(vb * 0.015625f);
            const __half a2a = __float2half_rn(va - 64.0f * __half2float(a1a));
            const __half a2b = __float2half_rn(vb - 64.0f * __half2float(a1b));
            u1[o2] = (uint32_t)__half_as_ushort(a1a) | ((uint32_t)__half_as_ushort(a1b) << 16);
            u2[o2] = (uint32_t)__half_as_ushort(a2a) | ((uint32_t)__half_as_ushort(a2b) << 16);
        }
        __half* d1 = p1 + (size_t)pos * 16;
        __half* d2 = p2 + (size_t)pos * 16;
        __stcs((uint4*)d1,       make_uint4(u1[0], u1[1], u1[2], u1[3]));
        __stcs((uint4*)(d1 + 8), make_uint4(u1[4], u1[5], u1[6], u1[7]));
        __stcs((uint4*)d2,       make_uint4(u2[0], u2[1], u2[2], u2[3]));
        __stcs((uint4*)(d2 + 8), make_uint4(u2[4], u2[5], u2[6], u2[7]));
    }
}

// ============================================================================
// Kernel 2: fc1 split-fp16 GEMM, split-K over 15 pieces + last-CTA reduction.
// Grid (4 N, 32 M, 15 K) = 1920 CTAs. Each writes its raw slice; the 15th
// arriver per tile sums slices 0..14 (fixed order), adds bias, ReLU -> g_y1,
// and resets the tile counter (graph-replay invariant).
// ============================================================================
__global__ __launch_bounds__(512) void fc1_mma(const float* __restrict__ bias)
{
    extern __shared__ __align__(1024) char smem[];
    __shared__ int sflag;
    const int tid = threadIdx.x;
    const int bx = blockIdx.x;   // N tile 0..3
    const int by = blockIdx.y;   // M tile 0..31
    const int kp = blockIdx.z;   // K piece 0..14
    const int warp = tid >> 5, lane = tid & 31;
    const int wm = warp >> 2;
    const int wn = warp & 3;
    const uint32_t sbase = smem_u32(smem);

    const __half* gp0 = g_A1 + (size_t)(by * 128) * K1;
    const __half* gp1 = g_A2 + (size_t)(by * 128) * K1;
    const __half* gp2 = g_W1 + (size_t)(bx * 128) * K1;
    const __half* gp3 = g_W2 + (size_t)(bx * 128) * K1;
    const int kbeg = kp * PSTG;

    auto issue_stage = [&](int kt, int slot) {
        const int k0 = kt * BK;
        const uint32_t sb = sbase + (uint32_t)slot * 65536u;
        #pragma unroll
        for (int p = 0; p < 8; p++) {
            const int plane = p >> 1;
            const int v = tid + ((p & 1) << 9);
            const int row = v >> 3;
            const int c = v & 7;
            const __half* g =
                (plane == 0 ? gp0 : plane == 1 ? gp1 : plane == 2 ? gp2 : gp3)
                + (size_t)row * K1 + k0 + c * 8;
            const uint32_t sa = sb + (uint32_t)plane * 16384u
                              + SWZ((uint32_t)(row * 128 + c * 16));
            asm volatile("cp.async.cg.shared.global [%0], [%1], 16;"
                         :: "r"(sa), "l"(g));
        }
        asm volatile("cp.async.commit_group;");
    };

    issue_stage(kbeg + 0, 0);
    issue_stage(kbeg + 1, 1);

    float acc[2][4][4];
    uint32_t hacc[2][4][2];
    #pragma unroll
    for (int i = 0; i < 2; i++)
        #pragma unroll
        for (int j = 0; j < 4; j++) {
            #pragma unroll
            for (int q = 0; q < 4; q++) acc[i][j][q] = 0.f;
            hacc[i][j][0] = 0u; hacc[i][j][1] = 0u;
        }

    const uint32_t a_row_off = (uint32_t)((wm * 32 + (lane & 15)) * 128);
    const uint32_t a_k_off   = (uint32_t)((lane >> 4) << 4);
    const uint32_t b_row_off = (uint32_t)((wn * 32 + ((lane >> 4) << 3) + (lane & 7)) * 128);
    const uint32_t b_k_off   = (uint32_t)(((lane >> 3) & 1) << 4);

    for (int it = 0; it < PSTG; it++) {
        asm volatile("cp.async.wait_group 1;");
        __syncthreads();
        if (it + 2 < PSTG) issue_stage(kbeg + it + 2, (it + 2) % STAGES);
        else asm volatile("cp.async.commit_group;");

        const uint32_t sb = sbase + (uint32_t)(it % STAGES) * 65536u;
        #pragma unroll
        for (int s = 0; s < 4; s++) {
            uint32_t a1f[2][4], a2f[2][4];
            #pragma unroll
            for (int mt = 0; mt < 2; mt++) {
                const uint32_t off = a_row_off + mt * 2048 + s * 32 + a_k_off;
                ldsm4(a1f[mt], sb + SWZ(off));
                ldsm4(a2f[mt], sb + 16384u + SWZ(off));
            }
            uint32_t w1f[2][4], w2f[2][4];
            #pragma unroll
            for (int q = 0; q < 2; q++) {
                const uint32_t off = b_row_off + q * 2048 + s * 32 + b_k_off;
                ldsm4(w1f[q], sb + 32768u + SWZ(off));
                ldsm4(w2f[q], sb + 49152u + SWZ(off));
            }
            #pragma unroll
            for (int mt = 0; mt < 2; mt++)
                #pragma unroll
                for (int nt = 0; nt < 4; nt++)
                    hmma_f32(acc[mt][nt], a1f[mt], &w1f[nt >> 1][(nt & 1) << 1]);
            #pragma unroll
            for (int mt = 0; mt < 2; mt++)
                #pragma unroll
                for (int nt = 0; nt < 4; nt++)
                    hmma_f16(hacc[mt][nt], a1f[mt], &w2f[nt >> 1][(nt & 1) << 1]);
            #pragma unroll
            for (int mt = 0; mt < 2; mt++)
                #pragma unroll
                for (int nt = 0; nt < 4; nt++)
                    hmma_f16(hacc[mt][nt], a2f[mt], &w1f[nt >> 1][(nt & 1) << 1]);
        }
    }

    // store raw slice
    float* ybase = g_y1s + (size_t)kp * N_SAMP * N1;
    #pragma unroll
    for (int mt = 0; mt < 2; mt++) {
        const int r0 = by * 128 + wm * 32 + mt * 16 + (lane >> 2);
        #pragma unroll
        for (int nt = 0; nt < 4; nt++) {
            const int c = bx * 128 + wn * 32 + nt * 8 + ((lane & 3) << 1);
            float2 c0 = __half22float2(*(half2*)&hacc[mt][nt][0]);
            float2 c1 = __half22float2(*(half2*)&hacc[mt][nt][1]);
            float2 v0, v1;
            v0.x = 64.0f * acc[mt][nt][0] + c0.x;
            v0.y = 64.0f * acc[mt][nt][1] + c0.y;
            v1.x = 64.0f * acc[mt][nt][2] + c1.x;
            v1.y = 64.0f * acc[mt][nt][3] + c1.y;
            __stcs((float2*)(ybase + (size_t)r0 * N1 + c), v0);
            __stcs((float2*)(ybase + (size_t)(r0 + 8) * N1 + c), v1);
        }
    }

    // last-CTA-per-tile reduction
    __threadfence();
    __syncthreads();
    const int tile = by * 4 + bx;
    if (tid == 0) {
        const int old = atomicAdd(&g_cnt[tile], 1);
        sflag = (old == KSPLIT - 1) ? 1 : 0;
        if (sflag) g_cnt[tile] = 0;  // reset for next graph replay
    }
    __syncthreads();
    if (sflag) {
        __threadfence();
        // sum 15 slices for this 128x128 tile, +bias, ReLU -> g_y1
        for (int e = tid; e < 4096; e += 512) {
            const int r = e >> 5;            // 0..127
            const int c4 = (e & 31) << 2;    // 0..124
            const size_t off = (size_t)(by * 128 + r) * N1 + bx * 128 + c4;
            float4 a = *(const float4*)(g_y1s + off);
            #pragma unroll
            for (int s = 1; s < KSPLIT; s++) {
                float4 t = *(const float4*)(g_y1s + (size_t)s * N_SAMP * N1 + off);
                a.x += t.x; a.y += t.y; a.z += t.z; a.w += t.w;
            }
            const int cc = bx * 128 + c4;
            a.x = fmaxf(a.x + __ldg(bias + cc + 0), 0.f);
            a.y = fmaxf(a.y + __ldg(bias + cc + 1), 0.f);
            a.z = fmaxf(a.z + __ldg(bias + cc + 2), 0.f);
            a.w = fmaxf(a.w + __ldg(bias + cc + 3), 0.f);
            *(float4*)(g_y1 + off) = a;
        }
    }
}

// ============================================================================
// Kernel 3: fused fc2(sigmoid) + fc3 -- 256 blocks of 16 rows, dense y1 input.
// ============================================================================
__global__ __launch_bounds__(256) void fc23_kernel(
    const float* __restrict__ w2, const float* __restrict__ b2,
    const float* __restrict__ w3, const float* __restrict__ b3,
    float* __restrict__ out)
{
    __shared__ float As[32][16];
    __shared__ float Bs[32][128];
    __shared__ float sbuf[16][128];
    __shared__ float sw3[128];

    const int tid = threadIdx.x;
    const int mb = blockIdx.x;
    const float* Ab = g_y1 + (size_t)(mb * 16) * N1;
    if (tid < 128) sw3[tid] = w3[tid];
    const int tm = tid >> 5;
    const int tn = tid & 31;

    float acc[2][4] = {};
    for (int kt = 0; kt < 16; kt++) {
        const int k0 = kt * 32;
        if (tid < 128) {
            const int row = tid >> 3, kq = (tid & 7) << 2;
            float4 a = *(const float4*)(Ab + (size_t)row * N1 + k0 + kq);
            As[kq + 0][row] = a.x; As[kq + 1][row] = a.y;
            As[kq + 2][row] = a.z; As[kq + 3][row] = a.w;
        }
        #pragma unroll
        for (int q = 0; q < 4; q++) {
            const int v = tid + q * 256;
            const int row = v >> 3, kq = (v & 7) << 2;
            float4 b = *(const float4*)(w2 + (size_t)row * N1 + k0 + kq);
            Bs[kq + 0][row] = b.x; Bs[kq + 1][row] = b.y;
            Bs[kq + 2][row] = b.z; Bs[kq + 3][row] = b.w;
        }
        __syncthreads();
        #pragma unroll
        for (int k = 0; k < 32; k++) {
            float ra[2], rb[4];
            ra[0] = As[k][tm * 2];
            ra[1] = As[k][tm * 2 + 1];
            *(float4*)rb = *(const float4*)&Bs[k][tn * 4];
            #pragma unroll
            for (int i = 0; i < 2; i++)
                #pragma unroll
                for (int j = 0; j < 4; j++) acc[i][j] += ra[i] * rb[j];
        }
        __syncthreads();
    }

    #pragma unroll
    for (int i = 0; i < 2; i++)
        #pragma unroll
        for (int j = 0; j < 4; j++) {
            const float v = acc[i][j] + b2[tn * 4 + j];
            sbuf[tm * 2 + i][tn * 4 + j] = 1.0f / (1.0f + expf(-v));
        }
    __syncthreads();

    #pragma unroll
    for (int r = 0; r < 2; r++) {
        const int row = tm * 2 + r;
        float s = sbuf[row][tn] * sw3[tn] + sbuf[row][tn + 32] * sw3[tn + 32]
                + sbuf[row][tn + 64] * sw3[tn + 64] + sbuf[row][tn + 96] * sw3[tn + 96];
        #pragma unroll
        for (int o = 16; o; o >>= 1) s += __shfl_down_sync(0xffffffffu, s, o);
        if (tn == 0) out[mb * 16 + row] = s + b3[0];
    }
}

// ============================================================================
extern "C" void kernel_launch(void* const* d_in, const int* in_sizes, int n_in,
                              void* d_out, int out_size) {
    const float* data   = (const float*)d_in[0];
    const float* gamma  = (const float*)d_in[1];
    const float* beta   = (const float*)d_in[2];
    const float* mean   = (const float*)d_in[3];
    const float* var    = (const float*)d_in[4];
    const float* conv_w = (const float*)d_in[5];
    const float* conv_b = (const float*)d_in[6];
    const float* fc1_w  = (const float*)d_in[7];
    const float* fc1_b  = (const float*)d_in[8];
    const float* fc2_w  = (const float*)d_in[9];
    const float* fc2_b  = (const float*)d_in[10];
    const float* fc3_w  = (const float*)d_in[11];
    const float* fc3_b  = (const float*)d_in[12];
    float* out = (float*)d_out;

    const int smem_sz = STAGES * 4 * 16384;  // 196608
    cudaFuncSetAttribute(fc1_mma, cudaFuncAttributeMaxDynamicSharedMemorySize, smem_sz);

    feat_kernel<<<N_SAMP + WBLK, 256>>>(data, gamma, beta, mean, var,
                                        conv_w, conv_b, fc1_w);
    dim3 g1(4, 32, KSPLIT);
    fc1_mma<<<g1, 512, smem_sz>>>(fc1_b);
    fc23_kernel<<<256, 256>>>(fc2_w, fc2_b, fc3_w, fc3_b, out);
}